// round 3
// baseline (speedup 1.0000x reference)
#include <cuda_runtime.h>

#define NUM_NODES  100000
#define NUM_GRAPHS 512
#define F1 128
#define F2 64
#define BN_EPS 1e-5f

// ---------------- scratch (static device globals; no allocation) ----------------
__device__ __align__(16) float g_deg [NUM_NODES];
__device__ __align__(16) float g_dis [NUM_NODES];
__device__ __align__(16) float g_xw1 [NUM_NODES * F1];
__device__ __align__(16) float g_acc1[NUM_NODES * F1];
__device__ __align__(16) float g_xw2 [NUM_NODES * F2];
__device__ __align__(16) float g_acc2[NUM_NODES * F2];
__device__ __align__(16) float g_pooled[NUM_GRAPHS * F2];
__device__ __align__(16) float g_mean[F2];
__device__ __align__(16) float g_rstd[F2];

// ---------------- degree / norm ----------------
__global__ void k_init(int n) {
    int i = blockIdx.x * blockDim.x + threadIdx.x;
    if (i < n) g_deg[i] = 1.0f;                 // self-loop contributes 1
    if (i < NUM_GRAPHS * F2) g_pooled[i] = 0.0f;
}

__global__ void k_deg(const int* __restrict__ dst, int E) {
    int e = blockIdx.x * blockDim.x + threadIdx.x;
    if (e < E) atomicAdd(&g_deg[dst[e]], 1.0f);
}

__global__ void k_dis(int n) {
    int i = blockIdx.x * blockDim.x + threadIdx.x;
    if (i < n) {
        float d = g_deg[i];
        g_dis[i] = (d > 0.f) ? rsqrtf(d) : 0.f;
    }
}

// ---------------- GEMM 1: xw1 = x @ W1   [N,128]x[128,128] ----------------
__global__ void k_gemm1(const float* __restrict__ x, const float* __restrict__ W, int n) {
    __shared__ float xs[64 * 128];
    int row0 = blockIdx.x * 64;
    int tid  = threadIdx.x;

    const float4* x4  = (const float4*)x;
    float4*       xs4 = (float4*)xs;
#pragma unroll
    for (int i = 0; i < 8; i++) {
        int idx = tid + i * 256;            // 0..2047 float4 (32 per row)
        int r   = idx >> 5;
        int row = row0 + r;
        xs4[idx] = (row < n) ? x4[(size_t)row * 32 + (idx & 31)]
                             : make_float4(0.f, 0.f, 0.f, 0.f);
    }
    __syncthreads();

    int colg  = tid & 31;          // *4 -> col
    int rbase = (tid >> 5) * 8;    // 8 rows per thread
    float4 acc[8];
#pragma unroll
    for (int i = 0; i < 8; i++) acc[i] = make_float4(0.f, 0.f, 0.f, 0.f);

    const float4* W4 = (const float4*)W;
    for (int k = 0; k < 128; k++) {
        float4 w = __ldg(&W4[k * 32 + colg]);
#pragma unroll
        for (int i = 0; i < 8; i++) {
            float a = xs[(rbase + i) * 128 + k];
            acc[i].x += a * w.x; acc[i].y += a * w.y;
            acc[i].z += a * w.z; acc[i].w += a * w.w;
        }
    }
#pragma unroll
    for (int i = 0; i < 8; i++) {
        int row = row0 + rbase + i;
        if (row < n)
            ((float4*)g_xw1)[(size_t)row * 32 + colg] = acc[i];
    }
}

// ---------------- self-loop init: acc1 = xw1 * dis^2 ----------------
__global__ void k_self1(int n4) {   // n4 = N*32 float4s
    int idx = blockIdx.x * blockDim.x + threadIdx.x;
    if (idx < n4) {
        int node = idx >> 5;
        float s = g_dis[node]; s = s * s;
        float4 v = ((const float4*)g_xw1)[idx];
        v.x *= s; v.y *= s; v.z *= s; v.w *= s;
        ((float4*)g_acc1)[idx] = v;
    }
}

// ---------------- edge scatter 1 (128 feats): warp per edge ----------------
__global__ void k_scatter1(const int* __restrict__ src,
                           const int* __restrict__ dst, int E) {
    int w    = (blockIdx.x * blockDim.x + threadIdx.x) >> 5;
    int lane = threadIdx.x & 31;
    if (w >= E) return;
    int s = src[w], d = dst[w];
    float norm = g_dis[s] * g_dis[d];
    float4 v = ((const float4*)(g_xw1 + (size_t)s * 128))[lane];
    float* p = g_acc1 + (size_t)d * 128 + lane * 4;
    atomicAdd(p + 0, v.x * norm);
    atomicAdd(p + 1, v.y * norm);
    atomicAdd(p + 2, v.z * norm);
    atomicAdd(p + 3, v.w * norm);
}

// ---------------- GEMM 2: xw2 = relu(acc1 + b1) @ W2  [N,128]x[128,64] -----
__global__ void k_gemm2(const float* __restrict__ W2, const float* __restrict__ b1, int n) {
    __shared__ float hs[64 * 128];
    __shared__ float b1s[128];
    int row0 = blockIdx.x * 64;
    int tid  = threadIdx.x;
    if (tid < 128) b1s[tid] = b1[tid];
    __syncthreads();

    const float4* a4  = (const float4*)g_acc1;
    float4*       hs4 = (float4*)hs;
#pragma unroll
    for (int i = 0; i < 8; i++) {
        int idx = tid + i * 256;
        int r   = idx >> 5;
        int k4  = idx & 31;
        int row = row0 + r;
        float4 v = (row < n) ? a4[(size_t)row * 32 + k4]
                             : make_float4(0.f, 0.f, 0.f, 0.f);
        v.x = fmaxf(v.x + b1s[k4 * 4 + 0], 0.f);
        v.y = fmaxf(v.y + b1s[k4 * 4 + 1], 0.f);
        v.z = fmaxf(v.z + b1s[k4 * 4 + 2], 0.f);
        v.w = fmaxf(v.w + b1s[k4 * 4 + 3], 0.f);
        hs4[idx] = v;
    }
    __syncthreads();

    int colg  = tid & 15;          // *4 -> 64 cols
    int rbase = (tid >> 4) * 4;    // 4 rows per thread, 16 groups -> 64 rows
    float4 acc[4];
#pragma unroll
    for (int i = 0; i < 4; i++) acc[i] = make_float4(0.f, 0.f, 0.f, 0.f);

    const float4* W4 = (const float4*)W2;
    for (int k = 0; k < 128; k++) {
        float4 w = __ldg(&W4[k * 16 + colg]);
#pragma unroll
        for (int i = 0; i < 4; i++) {
            float a = hs[(rbase + i) * 128 + k];
            acc[i].x += a * w.x; acc[i].y += a * w.y;
            acc[i].z += a * w.z; acc[i].w += a * w.w;
        }
    }
#pragma unroll
    for (int i = 0; i < 4; i++) {
        int row = row0 + rbase + i;
        if (row < n)
            ((float4*)g_xw2)[(size_t)row * 16 + colg] = acc[i];
    }
}

// ---------------- self-loop init 2: acc2 = xw2 * dis^2 ----------------
__global__ void k_self2(int n4) {   // n4 = N*16 float4s
    int idx = blockIdx.x * blockDim.x + threadIdx.x;
    if (idx < n4) {
        int node = idx >> 4;
        float s = g_dis[node]; s = s * s;
        float4 v = ((const float4*)g_xw2)[idx];
        v.x *= s; v.y *= s; v.z *= s; v.w *= s;
        ((float4*)g_acc2)[idx] = v;
    }
}

// ---------------- edge scatter 2 (64 feats): warp per edge, float2 ---------
__global__ void k_scatter2(const int* __restrict__ src,
                           const int* __restrict__ dst, int E) {
    int w    = (blockIdx.x * blockDim.x + threadIdx.x) >> 5;
    int lane = threadIdx.x & 31;
    if (w >= E) return;
    int s = src[w], d = dst[w];
    float norm = g_dis[s] * g_dis[d];
    float2 v = ((const float2*)(g_xw2 + (size_t)s * 64))[lane];
    float* p = g_acc2 + (size_t)d * 64 + lane * 2;
    atomicAdd(p + 0, v.x * norm);
    atomicAdd(p + 1, v.y * norm);
}

// ---------------- pooling: pooled[batch[i]] += relu(acc2[i] + b2) ----------
__global__ void k_pool(const int* __restrict__ batch,
                       const float* __restrict__ b2, int n) {
    int node = (blockIdx.x * blockDim.x + threadIdx.x) >> 5;
    int lane = threadIdx.x & 31;
    if (node >= n) return;
    int g = batch[node];
    float2 v = ((const float2*)(g_acc2 + (size_t)node * 64))[lane];
    float2 b = __ldg(&((const float2*)b2)[lane]);
    float a0 = fmaxf(v.x + b.x, 0.f);
    float a1 = fmaxf(v.y + b.y, 0.f);
    atomicAdd(&g_pooled[g * 64 + lane * 2 + 0], a0);
    atomicAdd(&g_pooled[g * 64 + lane * 2 + 1], a1);
}

// ---------------- BN statistics (population var, training mode) ------------
__global__ void k_bnstats() {
    int f = threadIdx.x;   // 64 threads
    float s = 0.f, q = 0.f;
    for (int g = 0; g < NUM_GRAPHS; g++) {
        float v = g_pooled[g * 64 + f];
        s += v; q += v * v;
    }
    float m   = s * (1.0f / NUM_GRAPHS);
    float var = q * (1.0f / NUM_GRAPHS) - m * m;
    g_mean[f] = m;
    g_rstd[f] = rsqrtf(var + BN_EPS);
}

// ---------------- head: BN affine + MLP; write (out, h) --------------------
__global__ void k_head(const float* __restrict__ gamma, const float* __restrict__ beta,
                       const float* __restrict__ Wo1,   const float* __restrict__ bo1,
                       const float* __restrict__ Wo2,   const float* __restrict__ bo2,
                       float* __restrict__ out) {
    int g = blockIdx.x * blockDim.x + threadIdx.x;
    if (g >= NUM_GRAPHS) return;
    float hid[24];
#pragma unroll
    for (int j = 0; j < 24; j++) hid[j] = __ldg(&bo1[j]);

    float* hout = out + NUM_GRAPHS + (size_t)g * 64;   // h = pooled (stop_gradient)
    for (int f = 0; f < 64; f++) {
        float p = g_pooled[g * 64 + f];
        hout[f] = p;
        float xn = (p - g_mean[f]) * g_rstd[f] * __ldg(&gamma[f]) + __ldg(&beta[f]);
#pragma unroll
        for (int j = 0; j < 24; j++)
            hid[j] += xn * __ldg(&Wo1[f * 24 + j]);
    }
    float o = __ldg(&bo2[0]);
#pragma unroll
    for (int j = 0; j < 24; j++)
        o += fmaxf(hid[j], 0.f) * __ldg(&Wo2[j]);
    out[g] = o;
}

// ---------------- launch ----------------
extern "C" void kernel_launch(void* const* d_in, const int* in_sizes, int n_in,
                              void* d_out, int out_size) {
    const float* x     = (const float*)d_in[0];
    const int*   ei    = (const int*)d_in[1];
    const int*   batch = (const int*)d_in[2];
    const float* W1    = (const float*)d_in[3];
    const float* b1    = (const float*)d_in[4];
    const float* W2    = (const float*)d_in[5];
    const float* b2    = (const float*)d_in[6];
    const float* gamma = (const float*)d_in[7];
    const float* beta  = (const float*)d_in[8];
    const float* Wo1   = (const float*)d_in[9];
    const float* bo1   = (const float*)d_in[10];
    const float* Wo2   = (const float*)d_in[11];
    const float* bo2   = (const float*)d_in[12];

    int N = in_sizes[0] / F1;
    int E = in_sizes[1] / 2;
    const int* src = ei;
    const int* dst = ei + E;
    float* out = (float*)d_out;

    k_init<<<(N + 255) / 256, 256>>>(N);
    k_deg <<<(E + 255) / 256, 256>>>(dst, E);
    k_dis <<<(N + 255) / 256, 256>>>(N);

    k_gemm1<<<(N + 63) / 64, 256>>>(x, W1, N);
    k_self1<<<(N * 32 + 255) / 256, 256>>>(N * 32);
    k_scatter1<<<(E + 7) / 8, 256>>>(src, dst, E);

    k_gemm2<<<(N + 63) / 64, 256>>>(W2, b1, N);
    k_self2<<<(N * 16 + 255) / 256, 256>>>(N * 16);
    k_scatter2<<<(E + 7) / 8, 256>>>(src, dst, E);

    k_pool<<<(N + 7) / 8, 256>>>(batch, b2, N);
    k_bnstats<<<1, 64>>>();
    k_head<<<(NUM_GRAPHS + 127) / 128, 128>>>(gamma, beta, Wo1, bo1, Wo2, bo2, out);
}

// round 4
// speedup vs baseline: 1.3939x; 1.3939x over previous
#include <cuda_runtime.h>

#define NUM_NODES  100000
#define NUM_GRAPHS 512
#define F1 128
#define F2 64
#define BN_EPS 1e-5f

// ---------------- scratch (static device globals; no allocation) ----------------
__device__ __align__(16) float g_deg [NUM_NODES];
__device__ __align__(16) float g_dis [NUM_NODES];
__device__ __align__(16) float g_xw1 [NUM_NODES * F1];
__device__ __align__(16) float g_acc1[NUM_NODES * F1];
__device__ __align__(16) float g_xw2 [NUM_NODES * F2];
__device__ __align__(16) float g_acc2[NUM_NODES * F2];
__device__ __align__(16) float g_pooled[NUM_GRAPHS * F2];
__device__ __align__(16) float g_mean[F2];
__device__ __align__(16) float g_rstd[F2];

// ---------------- vector reductions (sm_90+) ----------------
__device__ __forceinline__ void red_add_v4(float* p, float x, float y, float z, float w) {
    asm volatile("red.global.add.v4.f32 [%0], {%1,%2,%3,%4};"
                 :: "l"(p), "f"(x), "f"(y), "f"(z), "f"(w) : "memory");
}
__device__ __forceinline__ void red_add_v2(float* p, float x, float y) {
    asm volatile("red.global.add.v2.f32 [%0], {%1,%2};"
                 :: "l"(p), "f"(x), "f"(y) : "memory");
}

// ---------------- degree / norm ----------------
__global__ void k_init(int n) {
    int i = blockIdx.x * blockDim.x + threadIdx.x;
    if (i < n) g_deg[i] = 1.0f;                 // self-loop contributes 1
    if (i < NUM_GRAPHS * F2) g_pooled[i] = 0.0f;
}

__global__ void k_deg(const int* __restrict__ dst, int E) {
    int e = blockIdx.x * blockDim.x + threadIdx.x;
    if (e < E) atomicAdd(&g_deg[dst[e]], 1.0f);
}

__global__ void k_dis(int n) {
    int i = blockIdx.x * blockDim.x + threadIdx.x;
    if (i < n) {
        float d = g_deg[i];
        g_dis[i] = (d > 0.f) ? rsqrtf(d) : 0.f;
    }
}

// ---------------- GEMM 1: xw1 = x @ W1; acc1 = xw1*dis^2 (fused) -----------
__global__ void k_gemm1(const float* __restrict__ x, const float* __restrict__ W, int n) {
    __shared__ float xs[64 * 128];
    int row0 = blockIdx.x * 64;
    int tid  = threadIdx.x;

    const float4* x4  = (const float4*)x;
    float4*       xs4 = (float4*)xs;
#pragma unroll
    for (int i = 0; i < 8; i++) {
        int idx = tid + i * 256;            // 0..2047 float4 (32 per row)
        int r   = idx >> 5;
        int row = row0 + r;
        xs4[idx] = (row < n) ? x4[(size_t)row * 32 + (idx & 31)]
                             : make_float4(0.f, 0.f, 0.f, 0.f);
    }
    __syncthreads();

    int colg  = tid & 31;          // *4 -> col
    int rbase = (tid >> 5) * 8;    // 8 rows per thread
    float4 acc[8];
#pragma unroll
    for (int i = 0; i < 8; i++) acc[i] = make_float4(0.f, 0.f, 0.f, 0.f);

    const float4* W4 = (const float4*)W;
    for (int k = 0; k < 128; k++) {
        float4 w = __ldg(&W4[k * 32 + colg]);
#pragma unroll
        for (int i = 0; i < 8; i++) {
            float a = xs[(rbase + i) * 128 + k];
            acc[i].x += a * w.x; acc[i].y += a * w.y;
            acc[i].z += a * w.z; acc[i].w += a * w.w;
        }
    }
#pragma unroll
    for (int i = 0; i < 8; i++) {
        int row = row0 + rbase + i;
        if (row < n) {
            ((float4*)g_xw1)[(size_t)row * 32 + colg] = acc[i];
            float s = g_dis[row]; s = s * s;
            float4 v = acc[i];
            v.x *= s; v.y *= s; v.z *= s; v.w *= s;
            ((float4*)g_acc1)[(size_t)row * 32 + colg] = v;
        }
    }
}

// ---------------- edge scatter 1 (128 feats): warp per edge, red.v4 --------
__global__ void k_scatter1(const int* __restrict__ src,
                           const int* __restrict__ dst, int E) {
    int w    = (blockIdx.x * blockDim.x + threadIdx.x) >> 5;
    int lane = threadIdx.x & 31;
    if (w >= E) return;
    int s = src[w], d = dst[w];
    float norm = g_dis[s] * g_dis[d];
    float4 v = __ldg(&((const float4*)(g_xw1 + (size_t)s * 128))[lane]);
    float* p = g_acc1 + (size_t)d * 128 + lane * 4;
    red_add_v4(p, v.x * norm, v.y * norm, v.z * norm, v.w * norm);
}

// ---------------- GEMM 2: xw2 = relu(acc1+b1) @ W2; acc2 = xw2*dis^2 -------
__global__ void k_gemm2(const float* __restrict__ W2, const float* __restrict__ b1, int n) {
    __shared__ float hs[64 * 128];
    __shared__ float b1s[128];
    int row0 = blockIdx.x * 64;
    int tid  = threadIdx.x;
    if (tid < 128) b1s[tid] = b1[tid];
    __syncthreads();

    const float4* a4  = (const float4*)g_acc1;
    float4*       hs4 = (float4*)hs;
#pragma unroll
    for (int i = 0; i < 8; i++) {
        int idx = tid + i * 256;
        int r   = idx >> 5;
        int k4  = idx & 31;
        int row = row0 + r;
        float4 v = (row < n) ? a4[(size_t)row * 32 + k4]
                             : make_float4(0.f, 0.f, 0.f, 0.f);
        v.x = fmaxf(v.x + b1s[k4 * 4 + 0], 0.f);
        v.y = fmaxf(v.y + b1s[k4 * 4 + 1], 0.f);
        v.z = fmaxf(v.z + b1s[k4 * 4 + 2], 0.f);
        v.w = fmaxf(v.w + b1s[k4 * 4 + 3], 0.f);
        hs4[idx] = v;
    }
    __syncthreads();

    int colg  = tid & 15;          // *4 -> 64 cols
    int rbase = (tid >> 4) * 4;    // 4 rows per thread
    float4 acc[4];
#pragma unroll
    for (int i = 0; i < 4; i++) acc[i] = make_float4(0.f, 0.f, 0.f, 0.f);

    const float4* W4 = (const float4*)W2;
    for (int k = 0; k < 128; k++) {
        float4 w = __ldg(&W4[k * 16 + colg]);
#pragma unroll
        for (int i = 0; i < 4; i++) {
            float a = hs[(rbase + i) * 128 + k];
            acc[i].x += a * w.x; acc[i].y += a * w.y;
            acc[i].z += a * w.z; acc[i].w += a * w.w;
        }
    }
#pragma unroll
    for (int i = 0; i < 4; i++) {
        int row = row0 + rbase + i;
        if (row < n) {
            ((float4*)g_xw2)[(size_t)row * 16 + colg] = acc[i];
            float s = g_dis[row]; s = s * s;
            float4 v = acc[i];
            v.x *= s; v.y *= s; v.z *= s; v.w *= s;
            ((float4*)g_acc2)[(size_t)row * 16 + colg] = v;
        }
    }
}

// ---------------- edge scatter 2 (64 feats): warp per edge, red.v2 ---------
__global__ void k_scatter2(const int* __restrict__ src,
                           const int* __restrict__ dst, int E) {
    int w    = (blockIdx.x * blockDim.x + threadIdx.x) >> 5;
    int lane = threadIdx.x & 31;
    if (w >= E) return;
    int s = src[w], d = dst[w];
    float norm = g_dis[s] * g_dis[d];
    float2 v = __ldg(&((const float2*)(g_xw2 + (size_t)s * 64))[lane]);
    float* p = g_acc2 + (size_t)d * 64 + lane * 2;
    red_add_v2(p, v.x * norm, v.y * norm);
}

// ---------------- pooling: pooled[batch[i]] += relu(acc2[i] + b2) ----------
__global__ void k_pool(const int* __restrict__ batch,
                       const float* __restrict__ b2, int n) {
    int node = (blockIdx.x * blockDim.x + threadIdx.x) >> 5;
    int lane = threadIdx.x & 31;
    if (node >= n) return;
    int g = batch[node];
    float2 v = ((const float2*)(g_acc2 + (size_t)node * 64))[lane];
    float2 b = __ldg(&((const float2*)b2)[lane]);
    float a0 = fmaxf(v.x + b.x, 0.f);
    float a1 = fmaxf(v.y + b.y, 0.f);
    red_add_v2(&g_pooled[g * 64 + lane * 2], a0, a1);
}

// ---------------- BN statistics (population var, training mode) ------------
__global__ void k_bnstats() {
    int f = threadIdx.x;   // 64 threads
    float s = 0.f, q = 0.f;
    for (int g = 0; g < NUM_GRAPHS; g++) {
        float v = g_pooled[g * 64 + f];
        s += v; q += v * v;
    }
    float m   = s * (1.0f / NUM_GRAPHS);
    float var = q * (1.0f / NUM_GRAPHS) - m * m;
    g_mean[f] = m;
    g_rstd[f] = rsqrtf(var + BN_EPS);
}

// ---------------- head: BN affine + MLP; write (out, h) --------------------
__global__ void k_head(const float* __restrict__ gamma, const float* __restrict__ beta,
                       const float* __restrict__ Wo1,   const float* __restrict__ bo1,
                       const float* __restrict__ Wo2,   const float* __restrict__ bo2,
                       float* __restrict__ out) {
    int g = blockIdx.x * blockDim.x + threadIdx.x;
    if (g >= NUM_GRAPHS) return;
    float hid[24];
#pragma unroll
    for (int j = 0; j < 24; j++) hid[j] = __ldg(&bo1[j]);

    float* hout = out + NUM_GRAPHS + (size_t)g * 64;   // h = pooled (stop_gradient)
    for (int f = 0; f < 64; f++) {
        float p = g_pooled[g * 64 + f];
        hout[f] = p;
        float xn = (p - g_mean[f]) * g_rstd[f] * __ldg(&gamma[f]) + __ldg(&beta[f]);
#pragma unroll
        for (int j = 0; j < 24; j++)
            hid[j] += xn * __ldg(&Wo1[f * 24 + j]);
    }
    float o = __ldg(&bo2[0]);
#pragma unroll
    for (int j = 0; j < 24; j++)
        o += fmaxf(hid[j], 0.f) * __ldg(&Wo2[j]);
    out[g] = o;
}

// ---------------- launch ----------------
extern "C" void kernel_launch(void* const* d_in, const int* in_sizes, int n_in,
                              void* d_out, int out_size) {
    const float* x     = (const float*)d_in[0];
    const int*   ei    = (const int*)d_in[1];
    const int*   batch = (const int*)d_in[2];
    const float* W1    = (const float*)d_in[3];
    const float* b1    = (const float*)d_in[4];
    const float* W2    = (const float*)d_in[5];
    const float* b2    = (const float*)d_in[6];
    const float* gamma = (const float*)d_in[7];
    const float* beta  = (const float*)d_in[8];
    const float* Wo1   = (const float*)d_in[9];
    const float* bo1   = (const float*)d_in[10];
    const float* Wo2   = (const float*)d_in[11];
    const float* bo2   = (const float*)d_in[12];

    int N = in_sizes[0] / F1;
    int E = in_sizes[1] / 2;
    const int* src = ei;
    const int* dst = ei + E;
    float* out = (float*)d_out;

    k_init<<<(N + 255) / 256, 256>>>(N);
    k_deg <<<(E + 255) / 256, 256>>>(dst, E);
    k_dis <<<(N + 255) / 256, 256>>>(N);

    k_gemm1<<<(N + 63) / 64, 256>>>(x, W1, N);
    k_scatter1<<<(E + 7) / 8, 256>>>(src, dst, E);

    k_gemm2<<<(N + 63) / 64, 256>>>(W2, b1, N);
    k_scatter2<<<(E + 7) / 8, 256>>>(src, dst, E);

    k_pool<<<(N + 7) / 8, 256>>>(batch, b2, N);
    k_bnstats<<<1, 64>>>();
    k_head<<<(NUM_GRAPHS + 127) / 128, 128>>>(gamma, beta, Wo1, bo1, Wo2, bo2, out);
}

// round 5
// speedup vs baseline: 1.5278x; 1.0961x over previous
#include <cuda_runtime.h>

#define NUM_NODES  100000
#define MAX_EDGES  1700000
#define NUM_GRAPHS 512
#define F1 128
#define F2 64
#define BN_EPS 1e-5f

// ---------------- scratch (static device globals; no allocation) ----------------
__device__ __align__(16) int   g_cnt [NUM_NODES];     // edge count per dst
__device__ __align__(16) int   g_off [NUM_NODES];     // CSR start
__device__ __align__(16) int   g_cur [NUM_NODES];     // fill cursor
__device__ __align__(16) int   g_esrc[MAX_EDGES];     // src ids grouped by dst
__device__ __align__(16) float g_dis [NUM_NODES];
__device__ __align__(16) float g_xw1 [NUM_NODES * F1];
__device__ __align__(16) float g_acc1[NUM_NODES * F1];
__device__ __align__(16) float g_xw2 [NUM_NODES * F2];
__device__ __align__(16) float g_pooled[NUM_GRAPHS * F2];
__device__ __align__(16) float g_mean[F2];
__device__ __align__(16) float g_rstd[F2];

__device__ __forceinline__ void red_add_v2(float* p, float x, float y) {
    asm volatile("red.global.add.v2.f32 [%0], {%1,%2};"
                 :: "l"(p), "f"(x), "f"(y) : "memory");
}

// ---------------- CSR build ----------------
__global__ void k_init(int n) {
    int i = blockIdx.x * blockDim.x + threadIdx.x;
    if (i < n) g_cnt[i] = 0;
    if (i < NUM_GRAPHS * F2) g_pooled[i] = 0.0f;
}

__global__ void k_count(const int* __restrict__ dst, int E) {
    int e = blockIdx.x * blockDim.x + threadIdx.x;
    if (e < E) atomicAdd(&g_cnt[dst[e]], 1);
}

// single block, 1024 threads: exclusive scan of g_cnt -> g_off/g_cur, dis = rsqrt(cnt+1)
__global__ void k_scan(int n) {
    __shared__ int partial[1024];
    int tid = threadIdx.x;
    int ch  = (n + 1023) / 1024;
    int base = tid * ch;
    int sum = 0;
    for (int i = 0; i < ch; i++) {
        int idx = base + i;
        if (idx < n) sum += g_cnt[idx];
    }
    partial[tid] = sum;
    __syncthreads();
#pragma unroll
    for (int off = 1; off < 1024; off <<= 1) {
        int add = (tid >= off) ? partial[tid - off] : 0;
        __syncthreads();
        partial[tid] += add;
        __syncthreads();
    }
    int run = (tid > 0) ? partial[tid - 1] : 0;
    for (int i = 0; i < ch; i++) {
        int idx = base + i;
        if (idx < n) {
            int c = g_cnt[idx];
            g_off[idx] = run;
            g_cur[idx] = run;
            g_dis[idx] = rsqrtf((float)(c + 1));   // +1 self-loop
            run += c;
        }
    }
}

__global__ void k_fill(const int* __restrict__ src, const int* __restrict__ dst, int E) {
    int e = blockIdx.x * blockDim.x + threadIdx.x;
    if (e < E) {
        int slot = atomicAdd(&g_cur[dst[e]], 1);
        g_esrc[slot] = src[e];
    }
}

// ---------------- GEMM 1: xw1 = x @ W1   [N,128]x[128,128] ----------------
__global__ void k_gemm1(const float* __restrict__ x, const float* __restrict__ W, int n) {
    __shared__ float xs[64 * 128];
    int row0 = blockIdx.x * 64;
    int tid  = threadIdx.x;

    const float4* x4  = (const float4*)x;
    float4*       xs4 = (float4*)xs;
#pragma unroll
    for (int i = 0; i < 8; i++) {
        int idx = tid + i * 256;
        int r   = idx >> 5;
        int row = row0 + r;
        xs4[idx] = (row < n) ? x4[(size_t)row * 32 + (idx & 31)]
                             : make_float4(0.f, 0.f, 0.f, 0.f);
    }
    __syncthreads();

    int colg  = tid & 31;
    int rbase = (tid >> 5) * 8;
    float4 acc[8];
#pragma unroll
    for (int i = 0; i < 8; i++) acc[i] = make_float4(0.f, 0.f, 0.f, 0.f);

    const float4* W4 = (const float4*)W;
    for (int k = 0; k < 128; k++) {
        float4 w = __ldg(&W4[k * 32 + colg]);
#pragma unroll
        for (int i = 0; i < 8; i++) {
            float a = xs[(rbase + i) * 128 + k];
            acc[i].x += a * w.x; acc[i].y += a * w.y;
            acc[i].z += a * w.z; acc[i].w += a * w.w;
        }
    }
#pragma unroll
    for (int i = 0; i < 8; i++) {
        int row = row0 + rbase + i;
        if (row < n)
            ((float4*)g_xw1)[(size_t)row * 32 + colg] = acc[i];
    }
}

// ---------------- gather 1: acc1[d] = sum_{s in N(d)} xw1[s]*norm + self ----
__global__ void k_gather1(int n) {
    int d    = (blockIdx.x * blockDim.x + threadIdx.x) >> 5;
    int lane = threadIdx.x & 31;
    if (d >= n) return;
    int beg = g_off[d];
    int cnt = g_cnt[d];
    float dd = g_dis[d];

    const float4* self = (const float4*)(g_xw1 + (size_t)d * 128);
    float4 v = __ldg(&self[lane]);
    float sc = dd * dd;
    float4 acc = make_float4(v.x * sc, v.y * sc, v.z * sc, v.w * sc);

    for (int i = 0; i < cnt; i++) {
        int   s  = __ldg(&g_esrc[beg + i]);
        float nm = __ldg(&g_dis[s]) * dd;
        float4 u = __ldg(&((const float4*)(g_xw1 + (size_t)s * 128))[lane]);
        acc.x += u.x * nm; acc.y += u.y * nm;
        acc.z += u.z * nm; acc.w += u.w * nm;
    }
    ((float4*)(g_acc1 + (size_t)d * 128))[lane] = acc;
}

// ---------------- GEMM 2: xw2 = relu(acc1+b1) @ W2  [N,128]x[128,64] -------
__global__ void k_gemm2(const float* __restrict__ W2, const float* __restrict__ b1, int n) {
    __shared__ float hs[64 * 128];
    __shared__ float b1s[128];
    int row0 = blockIdx.x * 64;
    int tid  = threadIdx.x;
    if (tid < 128) b1s[tid] = b1[tid];
    __syncthreads();

    const float4* a4  = (const float4*)g_acc1;
    float4*       hs4 = (float4*)hs;
#pragma unroll
    for (int i = 0; i < 8; i++) {
        int idx = tid + i * 256;
        int r   = idx >> 5;
        int k4  = idx & 31;
        int row = row0 + r;
        float4 v = (row < n) ? a4[(size_t)row * 32 + k4]
                             : make_float4(0.f, 0.f, 0.f, 0.f);
        v.x = fmaxf(v.x + b1s[k4 * 4 + 0], 0.f);
        v.y = fmaxf(v.y + b1s[k4 * 4 + 1], 0.f);
        v.z = fmaxf(v.z + b1s[k4 * 4 + 2], 0.f);
        v.w = fmaxf(v.w + b1s[k4 * 4 + 3], 0.f);
        hs4[idx] = v;
    }
    __syncthreads();

    int colg  = tid & 15;
    int rbase = (tid >> 4) * 4;
    float4 acc[4];
#pragma unroll
    for (int i = 0; i < 4; i++) acc[i] = make_float4(0.f, 0.f, 0.f, 0.f);

    const float4* W4 = (const float4*)W2;
    for (int k = 0; k < 128; k++) {
        float4 w = __ldg(&W4[k * 16 + colg]);
#pragma unroll
        for (int i = 0; i < 4; i++) {
            float a = hs[(rbase + i) * 128 + k];
            acc[i].x += a * w.x; acc[i].y += a * w.y;
            acc[i].z += a * w.z; acc[i].w += a * w.w;
        }
    }
#pragma unroll
    for (int i = 0; i < 4; i++) {
        int row = row0 + rbase + i;
        if (row < n)
            ((float4*)g_xw2)[(size_t)row * 16 + colg] = acc[i];
    }
}

// ---- gather 2 + pool: pooled[batch[d]] += relu(gcn2[d] + b2)  (no acc2) ----
__global__ void k_gather2(const int* __restrict__ batch, const float* __restrict__ b2, int n) {
    int d    = (blockIdx.x * blockDim.x + threadIdx.x) >> 5;
    int lane = threadIdx.x & 31;
    if (d >= n) return;
    int beg = g_off[d];
    int cnt = g_cnt[d];
    float dd = g_dis[d];

    float2 v = __ldg(&((const float2*)(g_xw2 + (size_t)d * 64))[lane]);
    float sc = dd * dd;
    float accx = v.x * sc, accy = v.y * sc;

    for (int i = 0; i < cnt; i++) {
        int   s  = __ldg(&g_esrc[beg + i]);
        float nm = __ldg(&g_dis[s]) * dd;
        float2 u = __ldg(&((const float2*)(g_xw2 + (size_t)s * 64))[lane]);
        accx += u.x * nm; accy += u.y * nm;
    }
    float2 b = __ldg(&((const float2*)b2)[lane]);
    float a0 = fmaxf(accx + b.x, 0.f);
    float a1 = fmaxf(accy + b.y, 0.f);
    int g = __ldg(&batch[d]);
    red_add_v2(&g_pooled[g * 64 + lane * 2], a0, a1);
}

// ---------------- BN statistics ----------------
__global__ void k_bnstats() {
    int f = threadIdx.x;   // 64 threads
    float s = 0.f, q = 0.f;
    for (int g = 0; g < NUM_GRAPHS; g++) {
        float v = g_pooled[g * 64 + f];
        s += v; q += v * v;
    }
    float m   = s * (1.0f / NUM_GRAPHS);
    float var = q * (1.0f / NUM_GRAPHS) - m * m;
    g_mean[f] = m;
    g_rstd[f] = rsqrtf(var + BN_EPS);
}

// ---------------- head: BN affine + MLP; write (out, h) --------------------
__global__ void k_head(const float* __restrict__ gamma, const float* __restrict__ beta,
                       const float* __restrict__ Wo1,   const float* __restrict__ bo1,
                       const float* __restrict__ Wo2,   const float* __restrict__ bo2,
                       float* __restrict__ out) {
    int g = blockIdx.x * blockDim.x + threadIdx.x;
    if (g >= NUM_GRAPHS) return;
    float hid[24];
#pragma unroll
    for (int j = 0; j < 24; j++) hid[j] = __ldg(&bo1[j]);

    float* hout = out + NUM_GRAPHS + (size_t)g * 64;   // h = pooled (stop_gradient)
    for (int f = 0; f < 64; f++) {
        float p = g_pooled[g * 64 + f];
        hout[f] = p;
        float xn = (p - g_mean[f]) * g_rstd[f] * __ldg(&gamma[f]) + __ldg(&beta[f]);
#pragma unroll
        for (int j = 0; j < 24; j++)
            hid[j] += xn * __ldg(&Wo1[f * 24 + j]);
    }
    float o = __ldg(&bo2[0]);
#pragma unroll
    for (int j = 0; j < 24; j++)
        o += fmaxf(hid[j], 0.f) * __ldg(&Wo2[j]);
    out[g] = o;
}

// ---------------- launch ----------------
extern "C" void kernel_launch(void* const* d_in, const int* in_sizes, int n_in,
                              void* d_out, int out_size) {
    const float* x     = (const float*)d_in[0];
    const int*   ei    = (const int*)d_in[1];
    const int*   batch = (const int*)d_in[2];
    const float* W1    = (const float*)d_in[3];
    const float* b1    = (const float*)d_in[4];
    const float* W2    = (const float*)d_in[5];
    const float* b2    = (const float*)d_in[6];
    const float* gamma = (const float*)d_in[7];
    const float* beta  = (const float*)d_in[8];
    const float* Wo1   = (const float*)d_in[9];
    const float* bo1   = (const float*)d_in[10];
    const float* Wo2   = (const float*)d_in[11];
    const float* bo2   = (const float*)d_in[12];

    int N = in_sizes[0] / F1;
    int E = in_sizes[1] / 2;
    const int* src = ei;
    const int* dst = ei + E;
    float* out = (float*)d_out;

    k_init <<<(N + 255) / 256, 256>>>(N);
    k_count<<<(E + 255) / 256, 256>>>(dst, E);
    k_scan <<<1, 1024>>>(N);
    k_fill <<<(E + 255) / 256, 256>>>(src, dst, E);

    k_gemm1  <<<(N + 63) / 64, 256>>>(x, W1, N);
    k_gather1<<<(N + 7) / 8, 256>>>(N);

    k_gemm2  <<<(N + 63) / 64, 256>>>(W2, b1, N);
    k_gather2<<<(N + 7) / 8, 256>>>(batch, b2, N);

    k_bnstats<<<1, 64>>>();
    k_head<<<(NUM_GRAPHS + 127) / 128, 128>>>(gamma, beta, Wo1, bo1, Wo2, bo2, out);
}

// round 6
// speedup vs baseline: 1.5384x; 1.0069x over previous
#include <cuda_runtime.h>

#define NUM_NODES  100000
#define MAX_EDGES  1700000
#define NUM_GRAPHS 512
#define F1 128
#define F2 64
#define BN_EPS 1e-5f

// ---------------- scratch (static device globals; no allocation) ----------------
__device__ __align__(16) int   g_cnt [NUM_NODES];     // edge count per dst
__device__ __align__(16) int   g_off [NUM_NODES];     // CSR start
__device__ __align__(16) int   g_cur [NUM_NODES];     // fill cursor
__device__ __align__(16) int   g_esrc[MAX_EDGES];     // src ids grouped by dst
__device__ __align__(16) float g_dis [NUM_NODES];
__device__ __align__(16) float g_xw1 [NUM_NODES * F1];  // pre-scaled by dis[row]
__device__ __align__(16) float g_acc1[NUM_NODES * F1];
__device__ __align__(16) float g_xw2 [NUM_NODES * F2];  // pre-scaled by dis[row]
__device__ __align__(16) float g_pooled[NUM_GRAPHS * F2];
__device__ __align__(16) float g_mean[F2];
__device__ __align__(16) float g_rstd[F2];

__device__ __forceinline__ void red_add_v2(float* p, float x, float y) {
    asm volatile("red.global.add.v2.f32 [%0], {%1,%2};"
                 :: "l"(p), "f"(x), "f"(y) : "memory");
}

// ---------------- CSR build ----------------
__global__ void k_init(int n) {
    int i = blockIdx.x * blockDim.x + threadIdx.x;
    if (i < n) g_cnt[i] = 0;
    if (i < NUM_GRAPHS * F2) g_pooled[i] = 0.0f;
}

__global__ void k_count(const int* __restrict__ dst, int E) {
    int e = blockIdx.x * blockDim.x + threadIdx.x;
    if (e < E) atomicAdd(&g_cnt[dst[e]], 1);
}

// single block, 1024 threads: exclusive scan of g_cnt -> g_off/g_cur, dis = rsqrt(cnt+1)
__global__ void k_scan(int n) {
    __shared__ int partial[1024];
    int tid = threadIdx.x;
    int ch  = (n + 1023) / 1024;
    int base = tid * ch;
    int sum = 0;
    for (int i = 0; i < ch; i++) {
        int idx = base + i;
        if (idx < n) sum += g_cnt[idx];
    }
    partial[tid] = sum;
    __syncthreads();
#pragma unroll
    for (int off = 1; off < 1024; off <<= 1) {
        int add = (tid >= off) ? partial[tid - off] : 0;
        __syncthreads();
        partial[tid] += add;
        __syncthreads();
    }
    int run = (tid > 0) ? partial[tid - 1] : 0;
    for (int i = 0; i < ch; i++) {
        int idx = base + i;
        if (idx < n) {
            int c = g_cnt[idx];
            g_off[idx] = run;
            g_cur[idx] = run;
            g_dis[idx] = rsqrtf((float)(c + 1));   // +1 self-loop
            run += c;
        }
    }
}

__global__ void k_fill(const int* __restrict__ src, const int* __restrict__ dst, int E) {
    int e = blockIdx.x * blockDim.x + threadIdx.x;
    if (e < E) {
        int slot = atomicAdd(&g_cur[dst[e]], 1);
        g_esrc[slot] = src[e];
    }
}

// -------- GEMM 1: xw1' = (x @ W1) * dis[row]   [N,128]x[128,128] -----------
__global__ void k_gemm1(const float* __restrict__ x, const float* __restrict__ W, int n) {
    __shared__ float xs[64 * 128];
    int row0 = blockIdx.x * 64;
    int tid  = threadIdx.x;

    const float4* x4  = (const float4*)x;
    float4*       xs4 = (float4*)xs;
#pragma unroll
    for (int i = 0; i < 8; i++) {
        int idx = tid + i * 256;
        int r   = idx >> 5;
        int row = row0 + r;
        xs4[idx] = (row < n) ? x4[(size_t)row * 32 + (idx & 31)]
                             : make_float4(0.f, 0.f, 0.f, 0.f);
    }
    __syncthreads();

    int colg  = tid & 31;
    int rbase = (tid >> 5) * 8;
    float4 acc[8];
#pragma unroll
    for (int i = 0; i < 8; i++) acc[i] = make_float4(0.f, 0.f, 0.f, 0.f);

    const float4* W4 = (const float4*)W;
    for (int k = 0; k < 128; k++) {
        float4 w = __ldg(&W4[k * 32 + colg]);
#pragma unroll
        for (int i = 0; i < 8; i++) {
            float a = xs[(rbase + i) * 128 + k];
            acc[i].x += a * w.x; acc[i].y += a * w.y;
            acc[i].z += a * w.z; acc[i].w += a * w.w;
        }
    }
#pragma unroll
    for (int i = 0; i < 8; i++) {
        int row = row0 + rbase + i;
        if (row < n) {
            float s = g_dis[row];
            float4 v = acc[i];
            v.x *= s; v.y *= s; v.z *= s; v.w *= s;
            ((float4*)g_xw1)[(size_t)row * 32 + colg] = v;
        }
    }
}

// ---- gather 1: acc1[d] = dis[d] * (xw1'[d] + sum_{s in N(d)} xw1'[s]) ------
__global__ void k_gather1(int n) {
    int d    = (blockIdx.x * blockDim.x + threadIdx.x) >> 5;
    int lane = threadIdx.x & 31;
    if (d >= n) return;
    int beg = g_off[d];
    int cnt = g_cnt[d];
    float dd = g_dis[d];

    float4 acc = __ldg(&((const float4*)(g_xw1 + (size_t)d * 128))[lane]);

    const int* es = g_esrc + beg;
    int i = 0;
    for (; i + 4 <= cnt; i += 4) {
        int s0 = __ldg(&es[i + 0]);
        int s1 = __ldg(&es[i + 1]);
        int s2 = __ldg(&es[i + 2]);
        int s3 = __ldg(&es[i + 3]);
        float4 u0 = __ldg(&((const float4*)(g_xw1 + (size_t)s0 * 128))[lane]);
        float4 u1 = __ldg(&((const float4*)(g_xw1 + (size_t)s1 * 128))[lane]);
        float4 u2 = __ldg(&((const float4*)(g_xw1 + (size_t)s2 * 128))[lane]);
        float4 u3 = __ldg(&((const float4*)(g_xw1 + (size_t)s3 * 128))[lane]);
        acc.x += u0.x + u1.x + u2.x + u3.x;
        acc.y += u0.y + u1.y + u2.y + u3.y;
        acc.z += u0.z + u1.z + u2.z + u3.z;
        acc.w += u0.w + u1.w + u2.w + u3.w;
    }
    for (; i < cnt; i++) {
        int s = __ldg(&es[i]);
        float4 u = __ldg(&((const float4*)(g_xw1 + (size_t)s * 128))[lane]);
        acc.x += u.x; acc.y += u.y; acc.z += u.z; acc.w += u.w;
    }
    acc.x *= dd; acc.y *= dd; acc.z *= dd; acc.w *= dd;
    ((float4*)(g_acc1 + (size_t)d * 128))[lane] = acc;
}

// ---- GEMM 2: xw2' = (relu(acc1+b1) @ W2) * dis[row]  [N,128]x[128,64] -----
__global__ void k_gemm2(const float* __restrict__ W2, const float* __restrict__ b1, int n) {
    __shared__ float hs[64 * 128];
    __shared__ float b1s[128];
    int row0 = blockIdx.x * 64;
    int tid  = threadIdx.x;
    if (tid < 128) b1s[tid] = b1[tid];
    __syncthreads();

    const float4* a4  = (const float4*)g_acc1;
    float4*       hs4 = (float4*)hs;
#pragma unroll
    for (int i = 0; i < 8; i++) {
        int idx = tid + i * 256;
        int r   = idx >> 5;
        int k4  = idx & 31;
        int row = row0 + r;
        float4 v = (row < n) ? a4[(size_t)row * 32 + k4]
                             : make_float4(0.f, 0.f, 0.f, 0.f);
        v.x = fmaxf(v.x + b1s[k4 * 4 + 0], 0.f);
        v.y = fmaxf(v.y + b1s[k4 * 4 + 1], 0.f);
        v.z = fmaxf(v.z + b1s[k4 * 4 + 2], 0.f);
        v.w = fmaxf(v.w + b1s[k4 * 4 + 3], 0.f);
        hs4[idx] = v;
    }
    __syncthreads();

    int colg  = tid & 15;
    int rbase = (tid >> 4) * 4;
    float4 acc[4];
#pragma unroll
    for (int i = 0; i < 4; i++) acc[i] = make_float4(0.f, 0.f, 0.f, 0.f);

    const float4* W4 = (const float4*)W2;
    for (int k = 0; k < 128; k++) {
        float4 w = __ldg(&W4[k * 16 + colg]);
#pragma unroll
        for (int i = 0; i < 4; i++) {
            float a = hs[(rbase + i) * 128 + k];
            acc[i].x += a * w.x; acc[i].y += a * w.y;
            acc[i].z += a * w.z; acc[i].w += a * w.w;
        }
    }
#pragma unroll
    for (int i = 0; i < 4; i++) {
        int row = row0 + rbase + i;
        if (row < n) {
            float s = g_dis[row];
            float4 v = acc[i];
            v.x *= s; v.y *= s; v.z *= s; v.w *= s;
            ((float4*)g_xw2)[(size_t)row * 16 + colg] = v;
        }
    }
}

// ---- gather 2 + pool: pooled[batch[d]] += relu(dd*(self+sum) + b2) --------
__global__ void k_gather2(const int* __restrict__ batch, const float* __restrict__ b2, int n) {
    int d    = (blockIdx.x * blockDim.x + threadIdx.x) >> 5;
    int lane = threadIdx.x & 31;
    if (d >= n) return;
    int beg = g_off[d];
    int cnt = g_cnt[d];
    float dd = g_dis[d];

    float2 acc = __ldg(&((const float2*)(g_xw2 + (size_t)d * 64))[lane]);

    const int* es = g_esrc + beg;
    int i = 0;
    for (; i + 4 <= cnt; i += 4) {
        int s0 = __ldg(&es[i + 0]);
        int s1 = __ldg(&es[i + 1]);
        int s2 = __ldg(&es[i + 2]);
        int s3 = __ldg(&es[i + 3]);
        float2 u0 = __ldg(&((const float2*)(g_xw2 + (size_t)s0 * 64))[lane]);
        float2 u1 = __ldg(&((const float2*)(g_xw2 + (size_t)s1 * 64))[lane]);
        float2 u2 = __ldg(&((const float2*)(g_xw2 + (size_t)s2 * 64))[lane]);
        float2 u3 = __ldg(&((const float2*)(g_xw2 + (size_t)s3 * 64))[lane]);
        acc.x += u0.x + u1.x + u2.x + u3.x;
        acc.y += u0.y + u1.y + u2.y + u3.y;
    }
    for (; i < cnt; i++) {
        int s = __ldg(&es[i]);
        float2 u = __ldg(&((const float2*)(g_xw2 + (size_t)s * 64))[lane]);
        acc.x += u.x; acc.y += u.y;
    }
    float2 b = __ldg(&((const float2*)b2)[lane]);
    float a0 = fmaxf(acc.x * dd + b.x, 0.f);
    float a1 = fmaxf(acc.y * dd + b.y, 0.f);
    int g = __ldg(&batch[d]);
    red_add_v2(&g_pooled[g * 64 + lane * 2], a0, a1);
}

// ---------------- BN statistics: 256 threads = 64 feat x 4 groups ----------
__global__ void k_bnstats() {
    __shared__ float ssum[256], ssq[256];
    int f   = threadIdx.x & 63;
    int grp = threadIdx.x >> 6;     // 0..3
    float s = 0.f, q = 0.f;
    for (int g = grp; g < NUM_GRAPHS; g += 4) {
        float v = g_pooled[g * 64 + f];
        s += v; q += v * v;
    }
    ssum[threadIdx.x] = s; ssq[threadIdx.x] = q;
    __syncthreads();
    if (grp == 0) {
        s = ssum[f] + ssum[f + 64] + ssum[f + 128] + ssum[f + 192];
        q = ssq [f] + ssq [f + 64] + ssq [f + 128] + ssq [f + 192];
        float m   = s * (1.0f / NUM_GRAPHS);
        float var = q * (1.0f / NUM_GRAPHS) - m * m;
        g_mean[f] = m;
        g_rstd[f] = rsqrtf(var + BN_EPS);
    }
}

// ---------------- head: BN affine + MLP; write (out, h) --------------------
__global__ void k_head(const float* __restrict__ gamma, const float* __restrict__ beta,
                       const float* __restrict__ Wo1,   const float* __restrict__ bo1,
                       const float* __restrict__ Wo2,   const float* __restrict__ bo2,
                       float* __restrict__ out) {
    int g = blockIdx.x * blockDim.x + threadIdx.x;
    if (g >= NUM_GRAPHS) return;
    float hid[24];
#pragma unroll
    for (int j = 0; j < 24; j++) hid[j] = __ldg(&bo1[j]);

    float* hout = out + NUM_GRAPHS + (size_t)g * 64;   // h = pooled (stop_gradient)
    for (int f = 0; f < 64; f++) {
        float p = g_pooled[g * 64 + f];
        hout[f] = p;
        float xn = (p - g_mean[f]) * g_rstd[f] * __ldg(&gamma[f]) + __ldg(&beta[f]);
#pragma unroll
        for (int j = 0; j < 24; j++)
            hid[j] += xn * __ldg(&Wo1[f * 24 + j]);
    }
    float o = __ldg(&bo2[0]);
#pragma unroll
    for (int j = 0; j < 24; j++)
        o += fmaxf(hid[j], 0.f) * __ldg(&Wo2[j]);
    out[g] = o;
}

// ---------------- launch ----------------
extern "C" void kernel_launch(void* const* d_in, const int* in_sizes, int n_in,
                              void* d_out, int out_size) {
    const float* x     = (const float*)d_in[0];
    const int*   ei    = (const int*)d_in[1];
    const int*   batch = (const int*)d_in[2];
    const float* W1    = (const float*)d_in[3];
    const float* b1    = (const float*)d_in[4];
    const float* W2    = (const float*)d_in[5];
    const float* b2    = (const float*)d_in[6];
    const float* gamma = (const float*)d_in[7];
    const float* beta  = (const float*)d_in[8];
    const float* Wo1   = (const float*)d_in[9];
    const float* bo1   = (const float*)d_in[10];
    const float* Wo2   = (const float*)d_in[11];
    const float* bo2   = (const float*)d_in[12];

    int N = in_sizes[0] / F1;
    int E = in_sizes[1] / 2;
    const int* src = ei;
    const int* dst = ei + E;
    float* out = (float*)d_out;

    k_init <<<(N + 255) / 256, 256>>>(N);
    k_count<<<(E + 255) / 256, 256>>>(dst, E);
    k_scan <<<1, 1024>>>(N);
    k_fill <<<(E + 255) / 256, 256>>>(src, dst, E);

    k_gemm1  <<<(N + 63) / 64, 256>>>(x, W1, N);
    k_gather1<<<(N + 7) / 8, 256>>>(N);

    k_gemm2  <<<(N + 63) / 64, 256>>>(W2, b1, N);
    k_gather2<<<(N + 7) / 8, 256>>>(batch, b2, N);

    k_bnstats<<<1, 256>>>();
    k_head<<<(NUM_GRAPHS + 127) / 128, 128>>>(gamma, beta, Wo1, bo1, Wo2, bo2, out);
}